// round 5
// baseline (speedup 1.0000x reference)
#include <cuda_runtime.h>
#include <cuda_bf16.h>
#include <math.h>

// ---------------------------------------------------------------------------
// MolecularGNN fully fused. R4: 96-row tiles -> 3 CTAs/SM (occupancy),
// row&7 XOR swizzle (valid for stride-3 row tiling), norm fused into
// aggregation via warp shfl (norm pass deleted), u64 slot fetch.
// ---------------------------------------------------------------------------

#define MAX_T   524288
#define MAX_LAY 8
#define CAP     32
#define TILE_ROWS 96

__device__ unsigned      g_cnt[MAX_T];                  // zero-init (.bss)
__device__ unsigned char g_slots[(size_t)MAX_T * CAP];
__device__ float         g_Wt[MAX_LAY * 4096];

typedef unsigned long long u64;
__device__ __forceinline__ u64 pk2(float x, float y) {
    u64 r; asm("mov.b64 %0,{%1,%2};" : "=l"(r) : "f"(x), "f"(y)); return r;
}
__device__ __forceinline__ u64 bc2(float x) { return pk2(x, x); }
__device__ __forceinline__ void fma2(u64& d, u64 a, u64 b) {
    asm("fma.rn.f32x2 %0,%1,%2,%3;" : "=l"(d) : "l"(a), "l"(b), "l"(d));
}
__device__ __forceinline__ void up2(u64 v, float& x, float& y) {
    asm("mov.b64 {%0,%1},%2;" : "=f"(x), "=f"(y) : "l"(v));
}
// swizzled float-offset: quad q XOR (row & 7); valid for any row stride
// coprime with 8 (we use 3-row thread tiles)
__device__ __forceinline__ int vadr(int row, int q, int wo) {
    return row * 64 + (((q ^ (row & 7)) << 2) + wo);
}

// ---------------------------------------------------------------------------
__global__ void prep_kernel(const int* __restrict__ src,
                            const int* __restrict__ dst, int E, int S, int EB,
                            const float* __restrict__ Wfp,
                            const float* __restrict__ Wout, int LH) {
    int b = blockIdx.x;
    if (b < EB) {
        int e = b * 256 + threadIdx.x;
        if (e < E) {
            int d = dst[e];
            unsigned idx = atomicAdd(&g_cnt[d], 1u);
            if (idx < CAP) {
                int s = src[e];
                g_slots[(size_t)d * CAP + idx] = (unsigned char)(s - (s / S) * S);
            }
        }
    } else {
        int w = b - EB;
        const float* Ws = (w < LH) ? (Wfp + w * 4096) : (Wout + (w - LH) * 4096);
        float* o = g_Wt + w * 4096;
        for (int i = threadIdx.x; i < 4096; i += blockDim.x) {
            int k = i >> 6, j = i & 63;
            o[i] = Ws[j * 64 + k];
        }
    }
}

// ---------------------------------------------------------------------------
// smem floats: v 6144 | h 6144 | w 4096 | inv 128 | cnt 128 | fpx 128 |
//              slots 768 (3072B) | mb 32 (128B)      total 17568 f = 70272 B
__global__ __launch_bounds__(256, 3)
void gnn_fused_kernel(const int* __restrict__ fp,
                      const float* __restrict__ emb,
                      const float* __restrict__ b_fp,
                      const float* __restrict__ b_out,
                      const float* __restrict__ wprop,
                      const float* __restrict__ bprop,
                      const int* __restrict__ esrc,
                      const int* __restrict__ edst,
                      float* __restrict__ out,
                      int S, int G, int M, int E, int LH, int LO) {
    extern __shared__ float sm[];
    float* v_sh   = sm;                          // swizzled
    float* h_sh   = sm + 6144;                   // swizzled
    float* w_sh   = sm + 12288;                  // plain [k][c]
    float* inv_sh = sm + 16384;
    unsigned* cnt_sh = (unsigned*)(sm + 16512);
    int*      fpx_sh = (int*)(sm + 16640);
    unsigned char* slot_sh = (unsigned char*)(sm + 16768); // 3072 B
    unsigned char* mb_sh   = (unsigned char*)(sm + 17536); // 128 B

    const int t = threadIdx.x;
    const int molBase = blockIdx.x * G;
    const int Ga = min(G, M - molBase);
    if (Ga <= 0) return;
    const int GA = Ga * S;
    const int atomBase = molBase * S;

    const int tc8 = t & 7, trg = t >> 3;        // gemm: 8 colgroups x 32 rg
    const int c0a = tc8 * 4, c0b = c0a + 32, r0 = trg * 3;  // 3 rows/thread
    const int lane = t & 31, warp = t >> 5;
    const int aq = lane >> 1, awo = (lane & 1) * 2;          // agg col pairs

    // ---- stage adjacency, fp indices, mol bases, layer-0 weights ----
    {
        const u64* gs = (const u64*)(g_slots + (size_t)atomBase * CAP);
        u64* ss = (u64*)slot_sh;
        const int nQ = (GA * CAP) >> 3;
        for (int i = t; i < nQ; i += 256) ss[i] = gs[i];
        for (int r = t; r < GA; r += 256) {
            cnt_sh[r] = g_cnt[atomBase + r];
            g_cnt[atomBase + r] = 0u;
            fpx_sh[r] = fp[atomBase + r] * 16;
        }
        for (int r = t; r < TILE_ROWS; r += 256)
            mb_sh[r] = (unsigned char)((r / S) * S);
        if (t < 128) inv_sh[t] = 1.0f;          // layer-0 + pad rows
        const float4* ws = (const float4*)g_Wt;
        float4* wd = (float4*)w_sh;
        for (int i = t; i < 1024; i += 256) wd[i] = ws[i];
    }
    __syncthreads();

    // ---- embeddings (swizzled store, padded rows zeroed) ----
    {
        const float4* eq = (const float4*)emb;
        for (int idx = t; idx < GA * 16; idx += 256) {
            int r = idx >> 4, q = idx & 15;
            *(float4*)&v_sh[vadr(r, q, 0)] = eq[fpx_sh[r] + q];
        }
        const float4 z = make_float4(0.f, 0.f, 0.f, 0.f);
        for (int idx = GA * 16 + t; idx < TILE_ROWS * 16; idx += 256)
            *(float4*)&v_sh[vadr(idx >> 4, idx & 15, 0)] = z;
    }

    // ---- GNN layers ----
    for (int l = 0; l < LH; l++) {
        __syncthreads();            // v, w_sh(l), inv ready

        float ivr[3];
#pragma unroll
        for (int i = 0; i < 3; i++) ivr[i] = inv_sh[r0 + i];
        float4 bva = *(const float4*)(b_fp + l * 64 + c0a);
        float4 bvb = *(const float4*)(b_fp + l * 64 + c0b);

        // GEMM: h = relu((v*inv) @ Wt + b), 3 rows x 8 cols per thread
        u64 acc[3][4];
#pragma unroll
        for (int i = 0; i < 3; i++) {
            acc[i][0] = pk2(bva.x, bva.y); acc[i][1] = pk2(bva.z, bva.w);
            acc[i][2] = pk2(bvb.x, bvb.y); acc[i][3] = pk2(bvb.z, bvb.w);
        }
#pragma unroll 4
        for (int k = 0; k < 64; k += 4) {
            float vf[3][4];
#pragma unroll
            for (int i = 0; i < 3; i++) {
                int row = r0 + i;
                int co = (((k >> 2) ^ (row & 7)) << 2);
                *(float4*)vf[i] = *(const float4*)&v_sh[row * 64 + co];
            }
#pragma unroll
            for (int kk = 0; kk < 4; kk++) {
                ulonglong2 wa = *(const ulonglong2*)&w_sh[(k + kk) * 64 + c0a];
                ulonglong2 wb = *(const ulonglong2*)&w_sh[(k + kk) * 64 + c0b];
#pragma unroll
                for (int i = 0; i < 3; i++) {
                    u64 vb = bc2(vf[i][kk] * ivr[i]);
                    fma2(acc[i][0], vb, wa.x); fma2(acc[i][1], vb, wa.y);
                    fma2(acc[i][2], vb, wb.x); fma2(acc[i][3], vb, wb.y);
                }
            }
        }
#pragma unroll
        for (int i = 0; i < 3; i++) {
            float hv[8];
            up2(acc[i][0], hv[0], hv[1]); up2(acc[i][1], hv[2], hv[3]);
            up2(acc[i][2], hv[4], hv[5]); up2(acc[i][3], hv[6], hv[7]);
#pragma unroll
            for (int q = 0; q < 8; q++) hv[q] = fmaxf(hv[q], 0.f);
            int row = r0 + i;
            *(float4*)&h_sh[vadr(row, tc8, 0)]     = *(float4*)hv;
            *(float4*)&h_sh[vadr(row, tc8 + 8, 0)] = *(float4*)(hv + 4);
        }
        __syncthreads();

        // aggregation + fused norm: one warp per row
        for (int r = warp; r < GA; r += 8) {
            unsigned c = cnt_sh[r];
            int mb = mb_sh[r];
            float2 a = *(const float2*)&h_sh[vadr(r, aq, awo)];
            if (c <= CAP) {
                u64 s8 = *(const u64*)(slot_sh + r * CAP);  // first 8 slots
                unsigned c8 = min(c, 8u);
                for (unsigned e = 0; e < c8; e++) {
                    int nr = mb + (int)((s8 >> (e * 8)) & 0xFF);
                    float2 hh = *(const float2*)&h_sh[vadr(nr, aq, awo)];
                    a.x += hh.x; a.y += hh.y;
                }
                const unsigned char* sl = slot_sh + r * CAP;
                for (unsigned e = 8; e < c; e++) {
                    int nr = mb + sl[e];
                    float2 hh = *(const float2*)&h_sh[vadr(nr, aq, awo)];
                    a.x += hh.x; a.y += hh.y;
                }
            } else {            // unreachable for Poisson(4); correctness net
                int n = atomBase + r;
                for (int e = 0; e < E; e++)
                    if (edst[e] == n) {
                        int s = esrc[e];
                        int nr = mb + (s - (s / S) * S);
                        float2 hh = *(const float2*)&h_sh[vadr(nr, aq, awo)];
                        a.x += hh.x; a.y += hh.y;
                    }
            }
            // fused row-norm: 32 lanes hold the whole row
            float ss = a.x * a.x + a.y * a.y;
#pragma unroll
            for (int o = 16; o; o >>= 1) ss += __shfl_xor_sync(0xffffffffu, ss, o);
            if (lane == 0) inv_sh[r] = rsqrtf(fmaxf(ss, 1e-24f));
            *(float2*)&v_sh[vadr(r, aq, awo)] = a;
        }
        // stage next-layer weights (w_sh idle during agg epoch)
        {
            const float4* ws = (const float4*)(g_Wt + (l + 1) * 4096);
            float4* wd = (float4*)w_sh;
            for (int i = t; i < 1024; i += 256) wd[i] = ws[i];
        }
    }
    __syncthreads();    // v, inv(last) ready; w_sh = MLP layer 0

    // ---- molecule sums (apply final inv) ----
    for (int m = warp; m < Ga; m += 8) {
        float2 s = make_float2(0.f, 0.f);
        for (int i = 0; i < S; i++) {
            int r = m * S + i;
            float iv = inv_sh[r];
            float2 x = *(const float2*)&v_sh[vadr(r, aq, awo)];
            s.x = fmaf(x.x, iv, s.x); s.y = fmaf(x.y, iv, s.y);
        }
        *(float2*)&h_sh[m * 64 + lane * 2] = s;     // plain layout for MLP
    }

    // ---- output MLP (plain layout, few molecules) ----
    float* cur = h_sh;
    float* nxt = v_sh;
    for (int l = 0; l < LO; l++) {
        if (l > 0) {
            __syncthreads();
            const float4* ws = (const float4*)(g_Wt + (LH + l) * 4096);
            float4* wd = (float4*)w_sh;
            for (int i = t; i < 1024; i += 256) wd[i] = ws[i];
        }
        __syncthreads();
        for (int m = warp; m < Ga; m += 8) {
            float2 a = *(const float2*)&b_out[l * 64 + lane * 2];
#pragma unroll 8
            for (int k = 0; k < 64; k++) {
                float c = cur[m * 64 + k];
                float2 w2 = *(const float2*)&w_sh[k * 64 + lane * 2];
                a.x = fmaf(c, w2.x, a.x); a.y = fmaf(c, w2.y, a.y);
            }
            a.x = fmaxf(a.x, 0.f); a.y = fmaxf(a.y, 0.f);
            *(float2*)&nxt[m * 64 + lane * 2] = a;
        }
        float* tmp = cur; cur = nxt; nxt = tmp;
    }
    __syncthreads();

    // ---- final dot ----
    for (int m = warp; m < Ga; m += 8) {
        float s = cur[m * 64 + lane] * wprop[lane]
                + cur[m * 64 + 32 + lane] * wprop[32 + lane];
#pragma unroll
        for (int o = 16; o; o >>= 1) s += __shfl_xor_sync(0xffffffffu, s, o);
        if (lane == 0) out[molBase + m] = s + bprop[0];
    }
}

// ---------------------------------------------------------------------------

extern "C" void kernel_launch(void* const* d_in, const int* in_sizes, int n_in,
                              void* d_out, int out_size) {
    const float* emb    = (const float*)d_in[0];
    const float* W_fp   = (const float*)d_in[1];
    const float* b_fp   = (const float*)d_in[2];
    const float* W_out  = (const float*)d_in[3];
    const float* b_out  = (const float*)d_in[4];
    const float* W_prop = (const float*)d_in[5];
    const float* b_prop = (const float*)d_in[6];
    const int*   fp     = (const int*)d_in[7];
    const int*   esrc   = (const int*)d_in[8];
    const int*   edst   = (const int*)d_in[9];

    float* out = (float*)d_out;

    const int M  = out_size;
    const int T  = in_sizes[7];
    const int E  = in_sizes[8];
    const int LH = in_sizes[2] / 64;
    const int LO = in_sizes[4] / 64;
    const int S  = T / M;
    int G = TILE_ROWS / S;
    if (G < 1) G = 1;

    const int EB = (E + 255) / 256;
    prep_kernel<<<EB + LH + LO, 256>>>(esrc, edst, E, S, EB, W_fp, W_out, LH);

    const int smemBytes = 17568 * 4;        // 70272 B -> 3 CTAs/SM
    cudaFuncSetAttribute(gnn_fused_kernel,
                         cudaFuncAttributeMaxDynamicSharedMemorySize, smemBytes);
    const int nBlocks = (M + G - 1) / G;
    gnn_fused_kernel<<<nBlocks, 256, smemBytes>>>(fp, emb, b_fp, b_out,
                                                  W_prop, b_prop, esrc, edst, out,
                                                  S, G, M, E, LH, LO);
}

// round 7
// speedup vs baseline: 1.2760x; 1.2760x over previous
#include <cuda_runtime.h>
#include <math.h>
#include <cstdint>

// ---------------------------------------------------------------------------
// MolecularGNN fused, R6: layer GEMM on tensor cores via mma.sync tf32
// (compute_100-legal; tcgen05 is not, harness targets PTX compute_100).
// A = v tile (tf32-rounded fp32, quad-XOR swizzle), B = W as stored [n][k].
// ldmatrix.x4.b16 loads tf32 fragments (2xb16 = one 32b element per lane).
// ---------------------------------------------------------------------------

#define MAX_T 524288
#define MAX_LAY 8
#define CAP 32
#define TILE_ROWS 128

typedef unsigned long long u64;
typedef unsigned u32;

__device__ unsigned      g_cnt[MAX_T];                  // zero-init (.bss)
__device__ unsigned char g_slots[(size_t)MAX_T * CAP];
__device__ float         g_W [MAX_LAY * 4096];          // GNN W, tf32-rounded, [n][k]
__device__ float         g_Wt[MAX_LAY * 4096];          // MLP W, transposed [k][j]

__device__ __forceinline__ u32 cvt_tf32(float f) {
    u32 u; asm("cvt.rna.tf32.f32 %0, %1;" : "=r"(u) : "f"(f)); return u;
}
__device__ __forceinline__ float cvtf_tf32(float f) {
    return __uint_as_float(cvt_tf32(f));
}
// quad(16B)-XOR swizzled float offset; rows stride 64 floats
__device__ __forceinline__ int vadr(int r, int q, int wo) {
    return r * 64 + (((q ^ (r & 7)) << 2) + wo);
}
__device__ __forceinline__ u32 smem_u32(const void* p) {
    u32 a; asm("{ .reg .u64 t; cvta.to.shared.u64 t, %1; cvt.u32.u64 %0, t; }"
               : "=r"(a) : "l"(p));
    return a;
}
#define LDSM_X4(r0, r1, r2, r3, addr) \
    asm volatile("ldmatrix.sync.aligned.m8n8.x4.shared.b16 {%0,%1,%2,%3}, [%4];" \
                 : "=r"(r0), "=r"(r1), "=r"(r2), "=r"(r3) : "r"(addr))
#define MMA_TF32(c, a0, a1, a2, a3, b0, b1) \
    asm volatile("mma.sync.aligned.m16n8k8.row.col.f32.tf32.tf32.f32 " \
                 "{%0,%1,%2,%3},{%4,%5,%6,%7},{%8,%9},{%0,%1,%2,%3};" \
                 : "+f"((c)[0]), "+f"((c)[1]), "+f"((c)[2]), "+f"((c)[3]) \
                 : "r"(a0), "r"(a1), "r"(a2), "r"(a3), "r"(b0), "r"(b1))

// ---------------------------------------------------------------------------
__global__ void prep_kernel(const int* __restrict__ src,
                            const int* __restrict__ dst, int E, int S, int EB,
                            const float* __restrict__ Wfp,
                            const float* __restrict__ Wout, int LH) {
    int b = blockIdx.x;
    if (b < EB) {
        int e = b * 256 + threadIdx.x;
        if (e < E) {
            int d = dst[e];
            unsigned idx = atomicAdd(&g_cnt[d], 1u);
            if (idx < CAP) {
                int s = src[e];
                g_slots[(size_t)d * CAP + idx] = (unsigned char)(s - (s / S) * S);
            }
        }
    } else if (b < EB + LH) {
        int l = b - EB;                 // GNN W: tf32-round, keep [n][k]
        const float* Ws = Wfp + l * 4096;
        float* o = g_W + l * 4096;
        for (int i = threadIdx.x; i < 4096; i += blockDim.x)
            o[i] = cvtf_tf32(Ws[i]);
    } else {
        int l = b - EB - LH;            // MLP W: plain transpose
        const float* Ws = Wout + l * 4096;
        float* o = g_Wt + l * 4096;
        for (int i = threadIdx.x; i < 4096; i += blockDim.x) {
            int k = i >> 6, j = i & 63;
            o[i] = Ws[j * 64 + k];
        }
    }
}

// ---------------------------------------------------------------------------
// smem floats: A 8192 | H 8192 | Bw 4096 | bias 512 | cnt 128 | fpx 128 |
//              slots 1024 (4096B) | mb 32 (128B)  = 22304 f = 89216 B
#define SMEM_F 22304

__global__ __launch_bounds__(256, 2)
void gnn_fused_kernel(const int* __restrict__ fp,
                      const float* __restrict__ emb,
                      const float* __restrict__ b_fp,
                      const float* __restrict__ b_out,
                      const float* __restrict__ wprop,
                      const float* __restrict__ bprop,
                      const int* __restrict__ esrc,
                      const int* __restrict__ edst,
                      float* __restrict__ out,
                      int S, int G, int M, int E, int LH, int LO) {
    extern __shared__ float sm[];
    float* A      = sm;                          // v tile (swizzled) / MLP buf
    float* H      = sm + 8192;                   // h tile (swizzled)
    float* Bw     = sm + 16384;                  // weights (swizzled / plain)
    float* bias_sh = sm + 20480;                 // 512
    unsigned* cnt_sh = (unsigned*)(sm + 20992);  // 128
    int*      fpx_sh = (int*)(sm + 21120);       // 128
    unsigned char* slot_sh = (unsigned char*)(sm + 21248);  // 4096 B
    unsigned char* mb_sh   = (unsigned char*)(sm + 22272);  // 128 B

    const int t = threadIdx.x;
    const int warp = t >> 5, lane = t & 31;
    const int molBase = blockIdx.x * G;
    const int Ga = min(G, M - molBase);
    if (Ga <= 0) return;
    const int GA = Ga * S;
    const int atomBase = molBase * S;

    const u32 vbase = smem_u32(A);
    const u32 bbase = smem_u32(Bw);

    // ldmatrix lane geometry
    const int mi = lane >> 3, li = lane & 7;
    const int rA = warp * 16 + ((mi & 1) << 3) + li;    // A rows
    const int rB0 = ((mi >> 1) << 3) + li;              // B rows (+ g*16)
    const int qAofs = mi >> 1, qBofs = mi & 1;

    // ---- stage adjacency, fp idx, mol bases, biases, W(0) ----
    {
        const u64* gs = (const u64*)(g_slots + (size_t)atomBase * CAP);
        u64* ss = (u64*)slot_sh;
        const int nQ = (GA * CAP) >> 3;
        for (int i = t; i < nQ; i += 256) ss[i] = gs[i];
        for (int r = t; r < GA; r += 256) {
            cnt_sh[r] = g_cnt[atomBase + r];
            g_cnt[atomBase + r] = 0u;               // reset for next call
            fpx_sh[r] = fp[atomBase + r] * 16;
        }
        for (int r = t; r < TILE_ROWS; r += 256)
            mb_sh[r] = (unsigned char)((r / S) * S);
        if (t < LH * 64) bias_sh[t] = b_fp[t];
        // W(0) staged with quad swizzle
        const float4* ws = (const float4*)g_W;
        float4* wd = (float4*)Bw;
        for (int i = t; i < 1024; i += 256) {
            int n = i >> 4, q = i & 15;
            wd[(n << 4) + (q ^ (n & 7))] = ws[i];
        }
    }
    __syncthreads();

    // ---- embeddings into v tile (tf32-rounded, swizzled; pad rows zero) ----
    {
        const float4* eq = (const float4*)emb;
        for (int idx = t; idx < GA * 16; idx += 256) {
            int r = idx >> 4, q = idx & 15;
            float4 e = eq[fpx_sh[r] + q];
            e.x = cvtf_tf32(e.x); e.y = cvtf_tf32(e.y);
            e.z = cvtf_tf32(e.z); e.w = cvtf_tf32(e.w);
            *(float4*)&A[vadr(r, q, 0)] = e;
        }
        const float4 z = make_float4(0.f, 0.f, 0.f, 0.f);
        for (int idx = GA * 16 + t; idx < TILE_ROWS * 16; idx += 256)
            *(float4*)&A[vadr(idx >> 4, idx & 15, 0)] = z;
    }

    // ---- GNN layers ----
    for (int l = 0; l < LH; l++) {
        __syncthreads();            // v + Bw(l) ready; H free

        // GEMM on tensor cores: D[128,64] = A x W^T
        float C[8][4];
#pragma unroll
        for (int nt = 0; nt < 8; nt++)
#pragma unroll
            for (int i = 0; i < 4; i++) C[nt][i] = 0.f;

#pragma unroll
        for (int ks = 0; ks < 8; ks++) {
            u32 a0, a1, a2, a3;
            {
                int qA = ks * 2 + qAofs;
                u32 ad = vbase + 4u * (u32)vadr(rA, qA, 0);
                LDSM_X4(a0, a1, a2, a3, ad);
            }
            u32 bfr[4][4];
#pragma unroll
            for (int g = 0; g < 4; g++) {
                int rB = g * 16 + rB0;
                int qB = ks * 2 + qBofs;
                u32 ad = bbase + 4u * (u32)vadr(rB, qB, 0);
                LDSM_X4(bfr[g][0], bfr[g][1], bfr[g][2], bfr[g][3], ad);
            }
#pragma unroll
            for (int nt = 0; nt < 8; nt++) {
                int g = nt >> 1, s2 = (nt & 1) * 2;
                MMA_TF32(C[nt], a0, a1, a2, a3, bfr[g][s2], bfr[g][s2 + 1]);
            }
        }

        // epilogue: +bias, relu -> H (swizzled)
        {
            int er = warp * 16 + (lane >> 2);
            int ec = (lane & 3) * 2;
#pragma unroll
            for (int nt = 0; nt < 8; nt++) {
                int col = nt * 8 + ec;
                float2 bb = *(const float2*)&bias_sh[l * 64 + col];
                float2 h0, h1;
                h0.x = fmaxf(C[nt][0] + bb.x, 0.f);
                h0.y = fmaxf(C[nt][1] + bb.y, 0.f);
                h1.x = fmaxf(C[nt][2] + bb.x, 0.f);
                h1.y = fmaxf(C[nt][3] + bb.y, 0.f);
                *(float2*)&H[vadr(er,     col >> 2, col & 3)] = h0;
                *(float2*)&H[vadr(er + 8, col >> 2, col & 3)] = h1;
            }
        }
        __syncthreads();        // H complete; Bw free

        // aggregation + fused norm (one warp per row) -> v (tf32-rounded)
        const bool lastL = (l == LH - 1);
        const int aq = lane >> 1, awo = (lane & 1) * 2, c2 = lane * 2;
        for (int r = warp; r < GA; r += 8) {
            unsigned c = cnt_sh[r];
            int mb = mb_sh[r];
            float2 a = *(const float2*)&H[vadr(r, aq, awo)];
            if (c <= CAP) {
                u64 s8 = *(const u64*)(slot_sh + r * CAP);
                unsigned c8 = min(c, 8u);
                for (unsigned e = 0; e < c8; e++) {
                    int nr = mb + (int)((s8 >> (e * 8)) & 0xFF);
                    float2 hh = *(const float2*)&H[vadr(nr, aq, awo)];
                    a.x += hh.x; a.y += hh.y;
                }
                const unsigned char* sl = slot_sh + r * CAP;
                for (unsigned e = 8; e < c; e++) {
                    int nr = mb + sl[e];
                    float2 hh = *(const float2*)&H[vadr(nr, aq, awo)];
                    a.x += hh.x; a.y += hh.y;
                }
            } else {            // unreachable for Poisson(4); correctness net
                int n = atomBase + r;
                for (int e = 0; e < E; e++)
                    if (edst[e] == n) {
                        int s = esrc[e];
                        int nr = mb + (s - (s / S) * S);
                        float2 hh = *(const float2*)&H[vadr(nr, aq, awo)];
                        a.x += hh.x; a.y += hh.y;
                    }
            }
            float ss = a.x * a.x + a.y * a.y;
#pragma unroll
            for (int o = 16; o; o >>= 1) ss += __shfl_xor_sync(0xffffffffu, ss, o);
            float iv = rsqrtf(fmaxf(ss, 1e-24f));
            a.x *= iv; a.y *= iv;
            if (!lastL) {       // tf32-round for next MMA, swizzled layout
                float2 av; av.x = cvtf_tf32(a.x); av.y = cvtf_tf32(a.y);
                *(float2*)&A[vadr(r, aq, awo)] = av;
            } else {            // full fp32, plain layout for mol sums
                *(float2*)&A[r * 64 + c2] = a;
            }
        }
        // stage next weights (Bw free): next GNN layer (swizzled) or MLP0 (plain)
        if (l + 1 < LH) {
            const float4* ws = (const float4*)(g_W + (l + 1) * 4096);
            float4* wd = (float4*)Bw;
            for (int i = t; i < 1024; i += 256) {
                int n = i >> 4, q = i & 15;
                wd[(n << 4) + (q ^ (n & 7))] = ws[i];
            }
        } else {
            const float4* ws = (const float4*)g_Wt;
            float4* wd = (float4*)Bw;
            for (int i = t; i < 1024; i += 256) wd[i] = ws[i];
        }
    }
    __syncthreads();    // v plain + Bw = MLP layer 0

    // ---- molecule sums ----
    const int c2 = lane * 2;
    for (int m = warp; m < Ga; m += 8) {
        float2 s = make_float2(0.f, 0.f);
        for (int i = 0; i < S; i++) {
            float2 x = *(const float2*)&A[(m * S + i) * 64 + c2];
            s.x += x.x; s.y += x.y;
        }
        *(float2*)&H[m * 64 + c2] = s;
    }

    // ---- output MLP (plain layout) ----
    float* cur = H;
    float* nxt = A;
    for (int l = 0; l < LO; l++) {
        if (l > 0) {
            __syncthreads();
            const float4* ws = (const float4*)(g_Wt + l * 4096);
            float4* wd = (float4*)Bw;
            for (int i = t; i < 1024; i += 256) wd[i] = ws[i];
        }
        __syncthreads();
        for (int m = warp; m < Ga; m += 8) {
            float2 a = *(const float2*)&b_out[l * 64 + c2];
#pragma unroll 8
            for (int k = 0; k < 64; k++) {
                float cc = cur[m * 64 + k];
                float2 w2 = *(const float2*)&Bw[k * 64 + c2];
                a.x = fmaf(cc, w2.x, a.x); a.y = fmaf(cc, w2.y, a.y);
            }
            a.x = fmaxf(a.x, 0.f); a.y = fmaxf(a.y, 0.f);
            *(float2*)&nxt[m * 64 + c2] = a;
        }
        float* tmp = cur; cur = nxt; nxt = tmp;
    }
    __syncthreads();

    // ---- final dot ----
    for (int m = warp; m < Ga; m += 8) {
        float s = cur[m * 64 + lane] * wprop[lane]
                + cur[m * 64 + 32 + lane] * wprop[32 + lane];
#pragma unroll
        for (int o = 16; o; o >>= 1) s += __shfl_xor_sync(0xffffffffu, s, o);
        if (lane == 0) out[molBase + m] = s + bprop[0];
    }
}

// ---------------------------------------------------------------------------

extern "C" void kernel_launch(void* const* d_in, const int* in_sizes, int n_in,
                              void* d_out, int out_size) {
    const float* emb    = (const float*)d_in[0];
    const float* W_fp   = (const float*)d_in[1];
    const float* b_fp   = (const float*)d_in[2];
    const float* W_out  = (const float*)d_in[3];
    const float* b_out  = (const float*)d_in[4];
    const float* W_prop = (const float*)d_in[5];
    const float* b_prop = (const float*)d_in[6];
    const int*   fp     = (const int*)d_in[7];
    const int*   esrc   = (const int*)d_in[8];
    const int*   edst   = (const int*)d_in[9];

    float* out = (float*)d_out;

    const int M  = out_size;
    const int T  = in_sizes[7];
    const int E  = in_sizes[8];
    const int LH = in_sizes[2] / 64;
    const int LO = in_sizes[4] / 64;
    const int S  = T / M;
    int G = TILE_ROWS / S;
    if (G < 1) G = 1;

    const int EB = (E + 255) / 256;
    prep_kernel<<<EB + LH + LO, 256>>>(esrc, edst, E, S, EB, W_fp, W_out, LH);

    const int smemBytes = SMEM_F * 4;       // 89216 B
    cudaFuncSetAttribute(gnn_fused_kernel,
                         cudaFuncAttributeMaxDynamicSharedMemorySize, smemBytes);
    const int nBlocks = (M + G - 1) / G;
    gnn_fused_kernel<<<nBlocks, 256, smemBytes>>>(fp, emb, b_fp, b_out,
                                                  W_prop, b_prop, esrc, edst, out,
                                                  S, G, M, E, LH, LO);
}

// round 8
// speedup vs baseline: 1.2960x; 1.0157x over previous
#include <cuda_runtime.h>
#include <math.h>
#include <cstdint>

// ---------------------------------------------------------------------------
// MolecularGNN fused, R7: R6 (mma.sync tf32 GEMM) + latency-focused agg:
//  - slot lists padded to x4 (pad -> zeroed row 127): 4 independent loads/iter
//  - row-pair processing per warp: two shfl reduction chains overlapped
// ---------------------------------------------------------------------------

#define MAX_T 524288
#define MAX_LAY 8
#define CAP 32
#define TILE_ROWS 128

typedef unsigned long long u64;
typedef unsigned u32;

__device__ unsigned      g_cnt[MAX_T];                  // zero-init (.bss)
__device__ unsigned char g_slots[(size_t)MAX_T * CAP];
__device__ float         g_W [MAX_LAY * 4096];          // GNN W, tf32-rounded, [n][k]
__device__ float         g_Wt[MAX_LAY * 4096];          // MLP W, transposed [k][j]

__device__ __forceinline__ u32 cvt_tf32(float f) {
    u32 u; asm("cvt.rna.tf32.f32 %0, %1;" : "=r"(u) : "f"(f)); return u;
}
__device__ __forceinline__ float cvtf_tf32(float f) {
    return __uint_as_float(cvt_tf32(f));
}
__device__ __forceinline__ int vadr(int r, int q, int wo) {
    return r * 64 + (((q ^ (r & 7)) << 2) + wo);
}
__device__ __forceinline__ u32 smem_u32(const void* p) {
    u32 a; asm("{ .reg .u64 t; cvta.to.shared.u64 t, %1; cvt.u32.u64 %0, t; }"
               : "=r"(a) : "l"(p));
    return a;
}
#define LDSM_X4(r0, r1, r2, r3, addr) \
    asm volatile("ldmatrix.sync.aligned.m8n8.x4.shared.b16 {%0,%1,%2,%3}, [%4];" \
                 : "=r"(r0), "=r"(r1), "=r"(r2), "=r"(r3) : "r"(addr))
#define MMA_TF32(c, a0, a1, a2, a3, b0, b1) \
    asm volatile("mma.sync.aligned.m16n8k8.row.col.f32.tf32.tf32.f32 " \
                 "{%0,%1,%2,%3},{%4,%5,%6,%7},{%8,%9},{%0,%1,%2,%3};" \
                 : "+f"((c)[0]), "+f"((c)[1]), "+f"((c)[2]), "+f"((c)[3]) \
                 : "r"(a0), "r"(a1), "r"(a2), "r"(a3), "r"(b0), "r"(b1))

// ---------------------------------------------------------------------------
__global__ void prep_kernel(const int* __restrict__ src,
                            const int* __restrict__ dst, int E, int S, int EB,
                            const float* __restrict__ Wfp,
                            const float* __restrict__ Wout, int LH) {
    int b = blockIdx.x;
    if (b < EB) {
        int e = b * 256 + threadIdx.x;
        if (e < E) {
            int d = dst[e];
            unsigned idx = atomicAdd(&g_cnt[d], 1u);
            if (idx < CAP) {
                int s = src[e];
                g_slots[(size_t)d * CAP + idx] = (unsigned char)(s - (s / S) * S);
            }
        }
    } else if (b < EB + LH) {
        int l = b - EB;
        const float* Ws = Wfp + l * 4096;
        float* o = g_W + l * 4096;
        for (int i = threadIdx.x; i < 4096; i += blockDim.x)
            o[i] = cvtf_tf32(Ws[i]);
    } else {
        int l = b - EB - LH;
        const float* Ws = Wout + l * 4096;
        float* o = g_Wt + l * 4096;
        for (int i = threadIdx.x; i < 4096; i += blockDim.x) {
            int k = i >> 6, j = i & 63;
            o[i] = Ws[j * 64 + k];
        }
    }
}

// ---------------------------------------------------------------------------
// Gather one row's aggregate (h[r] + sum of neighbor h): counts padded to x4.
__device__ __forceinline__ float2 gather_row(
    const float* __restrict__ H, const unsigned char* __restrict__ slot_sh,
    const unsigned* __restrict__ cnt_sh, const unsigned char* __restrict__ mb_sh,
    int r, int aq, int awo, int atomBase, int S, int E,
    const int* __restrict__ esrc, const int* __restrict__ edst) {
    unsigned c = cnt_sh[r];
    int mb = mb_sh[r];
    float2 a = *(const float2*)&H[vadr(r, aq, awo)];
    if (c <= CAP) {
        const unsigned char* sl = slot_sh + r * CAP;
        float2 s1 = make_float2(0.f, 0.f), s2 = make_float2(0.f, 0.f),
               s3 = make_float2(0.f, 0.f);
        unsigned e = 0;
        for (; e + 4 <= c; e += 4) {
            u32 s4 = *(const u32*)(sl + e);
            int n0 = mb + (int)(s4 & 0xFF);
            int n1 = mb + (int)((s4 >> 8) & 0xFF);
            int n2 = mb + (int)((s4 >> 16) & 0xFF);
            int n3 = mb + (int)((s4 >> 24) & 0xFF);
            float2 h0 = *(const float2*)&H[vadr(n0, aq, awo)];
            float2 h1 = *(const float2*)&H[vadr(n1, aq, awo)];
            float2 h2 = *(const float2*)&H[vadr(n2, aq, awo)];
            float2 h3 = *(const float2*)&H[vadr(n3, aq, awo)];
            a.x += h0.x;  a.y += h0.y;
            s1.x += h1.x; s1.y += h1.y;
            s2.x += h2.x; s2.y += h2.y;
            s3.x += h3.x; s3.y += h3.y;
        }
        for (; e < c; e++) {                        // only if padding skipped
            int nr = mb + sl[e];
            float2 hh = *(const float2*)&H[vadr(nr, aq, awo)];
            a.x += hh.x; a.y += hh.y;
        }
        a.x += s1.x + s2.x + s3.x;
        a.y += s1.y + s2.y + s3.y;
    } else {                // unreachable for Poisson(4); correctness net
        int n = atomBase + r;
        for (int e = 0; e < E; e++)
            if (edst[e] == n) {
                int s = esrc[e];
                int nr = mb + (s - (s / S) * S);
                float2 hh = *(const float2*)&H[vadr(nr, aq, awo)];
                a.x += hh.x; a.y += hh.y;
            }
    }
    return a;
}

// ---------------------------------------------------------------------------
#define SMEM_F 22304

__global__ __launch_bounds__(256, 2)
void gnn_fused_kernel(const int* __restrict__ fp,
                      const float* __restrict__ emb,
                      const float* __restrict__ b_fp,
                      const float* __restrict__ b_out,
                      const float* __restrict__ wprop,
                      const float* __restrict__ bprop,
                      const int* __restrict__ esrc,
                      const int* __restrict__ edst,
                      float* __restrict__ out,
                      int S, int G, int M, int E, int LH, int LO) {
    extern __shared__ float sm[];
    float* A      = sm;
    float* H      = sm + 8192;
    float* Bw     = sm + 16384;
    float* bias_sh = sm + 20480;
    unsigned* cnt_sh = (unsigned*)(sm + 20992);
    int*      fpx_sh = (int*)(sm + 21120);
    unsigned char* slot_sh = (unsigned char*)(sm + 21248);
    unsigned char* mb_sh   = (unsigned char*)(sm + 22272);

    const int t = threadIdx.x;
    const int warp = t >> 5, lane = t & 31;
    const int molBase = blockIdx.x * G;
    const int Ga = min(G, M - molBase);
    if (Ga <= 0) return;
    const int GA = Ga * S;
    const int atomBase = molBase * S;
    const bool canPad = (GA < TILE_ROWS);   // row TILE_ROWS-1 usable as zero pad

    const u32 vbase = smem_u32(A);
    const u32 bbase = smem_u32(Bw);

    const int mi = lane >> 3, li = lane & 7;
    const int rA = warp * 16 + ((mi & 1) << 3) + li;
    const int rB0 = ((mi >> 1) << 3) + li;
    const int qAofs = mi >> 1, qBofs = mi & 1;

    // ---- stage adjacency, fp idx, mol bases, biases, W(0) ----
    {
        const u64* gs = (const u64*)(g_slots + (size_t)atomBase * CAP);
        u64* ss = (u64*)slot_sh;
        const int nQ = (GA * CAP) >> 3;
        for (int i = t; i < nQ; i += 256) ss[i] = gs[i];
        for (int r = t; r < GA; r += 256) {
            cnt_sh[r] = g_cnt[atomBase + r];
            g_cnt[atomBase + r] = 0u;
            fpx_sh[r] = fp[atomBase + r] * 16;
        }
        for (int r = t; r < TILE_ROWS; r += 256)
            mb_sh[r] = (unsigned char)((r / S) * S);
        if (t < LH * 64) bias_sh[t] = b_fp[t];
        const float4* ws = (const float4*)g_W;
        float4* wd = (float4*)Bw;
        for (int i = t; i < 1024; i += 256) {
            int n = i >> 4, q = i & 15;
            wd[(n << 4) + (q ^ (n & 7))] = ws[i];
        }
    }
    __syncthreads();

    // ---- pad slot lists to multiple of 4 (pad -> zero row 127) ----
    if (canPad) {
        for (int r = t; r < GA; r += 256) {
            unsigned c = cnt_sh[r];
            if (c <= CAP) {
                unsigned cp = (c + 3u) & ~3u;
                unsigned char padv = (unsigned char)((TILE_ROWS - 1) - mb_sh[r]);
                for (unsigned e = c; e < cp; e++) slot_sh[r * CAP + e] = padv;
                cnt_sh[r] = cp;
            }
        }
    }

    // ---- embeddings into v tile (tf32-rounded, swizzled; pad rows zero) ----
    {
        const float4* eq = (const float4*)emb;
        for (int idx = t; idx < GA * 16; idx += 256) {
            int r = idx >> 4, q = idx & 15;
            float4 e = eq[fpx_sh[r] + q];
            e.x = cvtf_tf32(e.x); e.y = cvtf_tf32(e.y);
            e.z = cvtf_tf32(e.z); e.w = cvtf_tf32(e.w);
            *(float4*)&A[vadr(r, q, 0)] = e;
        }
        const float4 z = make_float4(0.f, 0.f, 0.f, 0.f);
        for (int idx = GA * 16 + t; idx < TILE_ROWS * 16; idx += 256)
            *(float4*)&A[vadr(idx >> 4, idx & 15, 0)] = z;
    }

    // ---- GNN layers ----
    for (int l = 0; l < LH; l++) {
        __syncthreads();            // v + Bw(l) ready; H free

        float C[8][4];
#pragma unroll
        for (int nt = 0; nt < 8; nt++)
#pragma unroll
            for (int i = 0; i < 4; i++) C[nt][i] = 0.f;

#pragma unroll
        for (int ks = 0; ks < 8; ks++) {
            u32 a0, a1, a2, a3;
            {
                int qA = ks * 2 + qAofs;
                u32 ad = vbase + 4u * (u32)vadr(rA, qA, 0);
                LDSM_X4(a0, a1, a2, a3, ad);
            }
            u32 bfr[4][4];
#pragma unroll
            for (int g = 0; g < 4; g++) {
                int rB = g * 16 + rB0;
                int qB = ks * 2 + qBofs;
                u32 ad = bbase + 4u * (u32)vadr(rB, qB, 0);
                LDSM_X4(bfr[g][0], bfr[g][1], bfr[g][2], bfr[g][3], ad);
            }
#pragma unroll
            for (int nt = 0; nt < 8; nt++) {
                int g = nt >> 1, s2 = (nt & 1) * 2;
                MMA_TF32(C[nt], a0, a1, a2, a3, bfr[g][s2], bfr[g][s2 + 1]);
            }
        }

        // epilogue: +bias, relu -> H; force pad row 127 to zero
        {
            int er = warp * 16 + (lane >> 2);
            int ec = (lane & 3) * 2;
            const bool z1 = canPad && (er + 8 == TILE_ROWS - 1);
#pragma unroll
            for (int nt = 0; nt < 8; nt++) {
                int col = nt * 8 + ec;
                float2 bb = *(const float2*)&bias_sh[l * 64 + col];
                float2 h0, h1;
                h0.x = fmaxf(C[nt][0] + bb.x, 0.f);
                h0.y = fmaxf(C[nt][1] + bb.y, 0.f);
                h1.x = z1 ? 0.f : fmaxf(C[nt][2] + bb.x, 0.f);
                h1.y = z1 ? 0.f : fmaxf(C[nt][3] + bb.y, 0.f);
                *(float2*)&H[vadr(er,     col >> 2, col & 3)] = h0;
                *(float2*)&H[vadr(er + 8, col >> 2, col & 3)] = h1;
            }
        }
        __syncthreads();        // H complete; Bw free

        // aggregation + fused norm, row-pairs for shfl overlap
        const bool lastL = (l == LH - 1);
        const int aq = lane >> 1, awo = (lane & 1) * 2, c2 = lane * 2;
        for (int r = warp; r < GA; r += 16) {
            const int r2 = r + 8;
            const bool has2 = (r2 < GA);
            float2 aA = gather_row(H, slot_sh, cnt_sh, mb_sh, r, aq, awo,
                                   atomBase, S, E, esrc, edst);
            float2 aB = make_float2(0.f, 0.f);
            if (has2)
                aB = gather_row(H, slot_sh, cnt_sh, mb_sh, r2, aq, awo,
                                atomBase, S, E, esrc, edst);
            float sA = aA.x * aA.x + aA.y * aA.y;
            float sB = aB.x * aB.x + aB.y * aB.y;
#pragma unroll
            for (int o = 16; o; o >>= 1) {
                sA += __shfl_xor_sync(0xffffffffu, sA, o);
                sB += __shfl_xor_sync(0xffffffffu, sB, o);
            }
            float ivA = rsqrtf(fmaxf(sA, 1e-24f));
            float ivB = rsqrtf(fmaxf(sB, 1e-24f));
            aA.x *= ivA; aA.y *= ivA;
            aB.x *= ivB; aB.y *= ivB;
            if (!lastL) {
                float2 w1; w1.x = cvtf_tf32(aA.x); w1.y = cvtf_tf32(aA.y);
                *(float2*)&A[vadr(r, aq, awo)] = w1;
                if (has2) {
                    float2 w2; w2.x = cvtf_tf32(aB.x); w2.y = cvtf_tf32(aB.y);
                    *(float2*)&A[vadr(r2, aq, awo)] = w2;
                }
            } else {
                *(float2*)&A[r * 64 + c2] = aA;
                if (has2) *(float2*)&A[r2 * 64 + c2] = aB;
            }
        }
        // stage next weights
        if (l + 1 < LH) {
            const float4* ws = (const float4*)(g_W + (l + 1) * 4096);
            float4* wd = (float4*)Bw;
            for (int i = t; i < 1024; i += 256) {
                int n = i >> 4, q = i & 15;
                wd[(n << 4) + (q ^ (n & 7))] = ws[i];
            }
        } else {
            const float4* ws = (const float4*)g_Wt;
            float4* wd = (float4*)Bw;
            for (int i = t; i < 1024; i += 256) wd[i] = ws[i];
        }
    }
    __syncthreads();    // v plain + Bw = MLP layer 0

    // ---- molecule sums ----
    const int c2 = lane * 2;
    for (int m = warp; m < Ga; m += 8) {
        float2 s = make_float2(0.f, 0.f);
        for (int i = 0; i < S; i++) {
            float2 x = *(const float2*)&A[(m * S + i) * 64 + c2];
            s.x += x.x; s.y += x.y;
        }
        *(float2*)&H[m * 64 + c2] = s;
    }

    // ---- output MLP ----
    float* cur = H;
    float* nxt = A;
    for (int l = 0; l < LO; l++) {
        if (l > 0) {
            __syncthreads();
            const float4* ws = (const float4*)(g_Wt + l * 4096);
            float4* wd = (float4*)Bw;
            for (int i = t; i < 1024; i += 256) wd[i] = ws[i];
        }
        __syncthreads();
        for (int m = warp; m < Ga; m += 8) {
            float2 a = *(const float2*)&b_out[l * 64 + c2];
#pragma unroll 8
            for (int k = 0; k < 64; k++) {
                float cc = cur[m * 64 + k];
                float2 w2 = *(const float2*)&Bw[k * 64 + c2];
                a.x = fmaf(cc, w2.x, a.x); a.y = fmaf(cc, w2.y, a.y);
            }
            a.x = fmaxf(a.x, 0.f); a.y = fmaxf(a.y, 0.f);
            *(float2*)&nxt[m * 64 + c2] = a;
        }
        float* tmp = cur; cur = nxt; nxt = tmp;
    }
    __syncthreads();

    // ---- final dot ----
    for (int m = warp; m < Ga; m += 8) {
        float s = cur[m * 64 + lane] * wprop[lane]
                + cur[m * 64 + 32 + lane] * wprop[32 + lane];
#pragma unroll
        for (int o = 16; o; o >>= 1) s += __shfl_xor_sync(0xffffffffu, s, o);
        if (lane == 0) out[molBase + m] = s + bprop[0];
    }
}

// ---------------------------------------------------------------------------

extern "C" void kernel_launch(void* const* d_in, const int* in_sizes, int n_in,
                              void* d_out, int out_size) {
    const float* emb    = (const float*)d_in[0];
    const float* W_fp   = (const float*)d_in[1];
    const float* b_fp   = (const float*)d_in[2];
    const float* W_out  = (const float*)d_in[3];
    const float* b_out  = (const float*)d_in[4];
    const float* W_prop = (const float*)d_in[5];
    const float* b_prop = (const float*)d_in[6];
    const int*   fp     = (const int*)d_in[7];
    const int*   esrc   = (const int*)d_in[8];
    const int*   edst   = (const int*)d_in[9];

    float* out = (float*)d_out;

    const int M  = out_size;
    const int T  = in_sizes[7];
    const int E  = in_sizes[8];
    const int LH = in_sizes[2] / 64;
    const int LO = in_sizes[4] / 64;
    const int S  = T / M;
    int G = TILE_ROWS / S;
    if (G < 1) G = 1;

    const int EB = (E + 255) / 256;
    prep_kernel<<<EB + LH + LO, 256>>>(esrc, edst, E, S, EB, W_fp, W_out, LH);

    const int smemBytes = SMEM_F * 4;
    cudaFuncSetAttribute(gnn_fused_kernel,
                         cudaFuncAttributeMaxDynamicSharedMemorySize, smemBytes);
    const int nBlocks = (M + G - 1) / G;
    gnn_fused_kernel<<<nBlocks, 256, smemBytes>>>(fp, emb, b_fp, b_out,
                                                  W_prop, b_prop, esrc, edst, out,
                                                  S, G, M, E, LH, LO);
}